// round 17
// baseline (speedup 1.0000x reference)
#include <cuda_runtime.h>
#include <cstdint>

// Problem constants (GCN_59846074302981): N=50000, E=800000, F=H=128, C=8
#define MAX_N 50000
#define MAX_E 800000

// ---------------------------------------------------------------------------
// Scratch (allocation-free device globals).
// RULE (round 10): device globals referenced ONLY inside kernel bodies.
// Linear collapse: out = A·(A·(X@Wall) + c1) + c2,
//   Wall = W1@W2@Wfc [128x8], c1 = b1@(W2@Wfc) [8], c2 = b2@Wfc + bfc [8]
// ---------------------------------------------------------------------------
__device__ __align__(16) float g_z0[MAX_N * 8];    // X @ Wall
__device__ __align__(16) float g_z1[MAX_N * 8];    // A z0 + c1
__device__ __align__(16) float g_wall[128 * 8];
__device__ __align__(16) float g_c1[8];
__device__ __align__(16) float g_c2[8];
__device__ __align__(16) float g_dinv[MAX_N];
__device__ int g_deg[MAX_N];
__device__ int g_stride;                           // 1 = int32 edges, 2 = int64

// ---------------------------------------------------------------------------
// init: zero degrees; warp 0 of block 0 probes edge dtype in parallel.
// ---------------------------------------------------------------------------
__global__ void k_init(const int* __restrict__ ebuf, int n) {
    int i = blockIdx.x * blockDim.x + threadIdx.x;
    if (i < n) g_deg[i] = 0;
    if (blockIdx.x == 0 && threadIdx.x < 32) {
        int lane = threadIdx.x;
        int nz = 0;
        #pragma unroll
        for (int t = 0; t < 8; t++)
            nz |= ebuf[2 * (lane + 32 * t) + 1];
        unsigned m = __ballot_sync(0xffffffffu, nz != 0);
        if (lane == 0) g_stride = (m == 0) ? 2 : 1;
    }
}

__global__ void k_hist(const int* __restrict__ ebuf, int e, int n) {
    int i = blockIdx.x * blockDim.x + threadIdx.x;
    if (i >= e) return;
    int st = g_stride;
    int c = ebuf[((long)e + i) * st];
    if ((unsigned)c < (unsigned)n) atomicAdd(&g_deg[c], 1);
}

// ---------------------------------------------------------------------------
// Fused weight collapse (one kernel, 129 blocks):
// Every block computes T = W2@Wfc into smem (redundant, cheap, L2-hot).
//   blocks 0..127 : warp w writes Wall[b][w] = sum_j W1[b][j]*T[j][w]
//   block 128     : warp w writes c1[w] = b1@T[:,w],
//                   c2[w] = b2@Wfc[:,w] + bfc[w]
// ---------------------------------------------------------------------------
__global__ __launch_bounds__(256) void k_prep2(const float* __restrict__ W1,
                                               const float* __restrict__ W2,
                                               const float* __restrict__ Wfc,
                                               const float* __restrict__ b1,
                                               const float* __restrict__ b2,
                                               const float* __restrict__ bfc) {
    __shared__ __align__(16) float sWfc[128 * 8];
    __shared__ __align__(16) float sT[128 * 8];
    int tid = threadIdx.x;

    #pragma unroll
    for (int p = 0; p < 4; p++) sWfc[tid + p * 256] = Wfc[tid + p * 256];
    __syncthreads();

    // T: thread computes 4 outputs (same column c, rows j0+32p)
    {
        int c  = tid & 7;
        int j0 = tid >> 3;                 // 0..31
        float acc0 = 0.f, acc1 = 0.f, acc2 = 0.f, acc3 = 0.f;
        #pragma unroll 4
        for (int jj = 0; jj < 128; jj++) {
            float f = sWfc[jj * 8 + c];
            acc0 += W2[(j0 +  0) * 128 + jj] * f;
            acc1 += W2[(j0 + 32) * 128 + jj] * f;
            acc2 += W2[(j0 + 64) * 128 + jj] * f;
            acc3 += W2[(j0 + 96) * 128 + jj] * f;
        }
        sT[(j0 +  0) * 8 + c] = acc0;
        sT[(j0 + 32) * 8 + c] = acc1;
        sT[(j0 + 64) * 8 + c] = acc2;
        sT[(j0 + 96) * 8 + c] = acc3;
    }
    __syncthreads();

    int warp = tid >> 5, lane = tid & 31;
    int jl = lane << 2;
    int b = blockIdx.x;

    if (b < 128) {
        float4 w = reinterpret_cast<const float4*>(W1)[b * 32 + lane];
        float s = w.x * sT[(jl + 0) * 8 + warp] + w.y * sT[(jl + 1) * 8 + warp]
                + w.z * sT[(jl + 2) * 8 + warp] + w.w * sT[(jl + 3) * 8 + warp];
        #pragma unroll
        for (int o = 16; o > 0; o >>= 1) s += __shfl_xor_sync(0xffffffffu, s, o);
        if (lane == 0) g_wall[b * 8 + warp] = s;
    } else {
        float4 v1 = reinterpret_cast<const float4*>(b1)[lane];
        float s1 = v1.x * sT[(jl + 0) * 8 + warp] + v1.y * sT[(jl + 1) * 8 + warp]
                 + v1.z * sT[(jl + 2) * 8 + warp] + v1.w * sT[(jl + 3) * 8 + warp];
        float4 v2 = reinterpret_cast<const float4*>(b2)[lane];
        float s2 = v2.x * sWfc[(jl + 0) * 8 + warp] + v2.y * sWfc[(jl + 1) * 8 + warp]
                 + v2.z * sWfc[(jl + 2) * 8 + warp] + v2.w * sWfc[(jl + 3) * 8 + warp];
        #pragma unroll
        for (int o = 16; o > 0; o >>= 1) {
            s1 += __shfl_xor_sync(0xffffffffu, s1, o);
            s2 += __shfl_xor_sync(0xffffffffu, s2, o);
        }
        if (lane == 0) {
            g_c1[warp] = s1;
            g_c2[warp] = s2 + bfc[warp];
        }
    }
}

// ---------------------------------------------------------------------------
// z0 = X @ Wall [n,8]; z1 = c1 + dinv^2 * z0 (layer-1 self-loop);
// dinv = rsqrt(deg+1) computed here; ALSO pre-writes out = c2 so the
// phase-1 scatter (with virtual self-edges) can accumulate everything else.
// One warp per row: lane holds X[row][4*lane..4*lane+3], butterfly reduce.
// ---------------------------------------------------------------------------
__global__ __launch_bounds__(256) void k_gz0(const float* __restrict__ X,
                                             float* __restrict__ outp, int n) {
    __shared__ __align__(16) float wsT[8][128];   // [c][k]
    __shared__ float c1s[8];
    __shared__ float c2s[8];
    int tid = threadIdx.x;

    for (int i = tid; i < 1024; i += 256) {
        int k = i >> 3, c = i & 7;
        wsT[c][k] = g_wall[i];
    }
    if (tid < 8)  c1s[tid] = g_c1[tid];
    if (tid < 8)  c2s[tid] = g_c2[tid];
    __syncthreads();

    int warp = blockIdx.x * 8 + (tid >> 5);
    int lane = tid & 31;
    if (warp >= n) return;

    float4 xv = reinterpret_cast<const float4*>(X)[(long)warp * 32 + lane];
    int k0 = lane << 2;

    float p[8];
    #pragma unroll
    for (int c = 0; c < 8; c++) {
        float4 w = *reinterpret_cast<const float4*>(&wsT[c][k0]);
        p[c] = xv.x * w.x + xv.y * w.y + xv.z * w.z + xv.w * w.w;
    }
    #pragma unroll
    for (int o = 16; o > 0; o >>= 1)
        #pragma unroll
        for (int c = 0; c < 8; c++)
            p[c] += __shfl_xor_sync(0xffffffffu, p[c], o);

    if (lane == 0) {
        float d = rsqrtf((float)g_deg[warp] + 1.0f);   // +1 self-loop
        g_dinv[warp] = d;
        float s = d * d;
        reinterpret_cast<float4*>(g_z0)[(long)warp * 2 + 0] =
            make_float4(p[0], p[1], p[2], p[3]);
        reinterpret_cast<float4*>(g_z0)[(long)warp * 2 + 1] =
            make_float4(p[4], p[5], p[6], p[7]);
        reinterpret_cast<float4*>(g_z1)[(long)warp * 2 + 0] =
            make_float4(c1s[0] + s * p[0], c1s[1] + s * p[1],
                        c1s[2] + s * p[2], c1s[3] + s * p[3]);
        reinterpret_cast<float4*>(g_z1)[(long)warp * 2 + 1] =
            make_float4(c1s[4] + s * p[4], c1s[5] + s * p[5],
                        c1s[6] + s * p[6], c1s[7] + s * p[7]);
        // out = c2 (base for phase-1 scatter accumulation)
        reinterpret_cast<float4*>(outp)[(long)warp * 2 + 0] =
            make_float4(c2s[0], c2s[1], c2s[2], c2s[3]);
        reinterpret_cast<float4*>(outp)[(long)warp * 2 + 1] =
            make_float4(c2s[4], c2s[5], c2s[6], c2s[7]);
    }
}

// ---------------------------------------------------------------------------
// Scatter: dst[col][0..7] += dinv[row]*dinv[col] * src[row][0..7].
// 2 threads per edge; each packs one half (16B) into one red.global.add.v4.f32.
// Work items: [0,e) real edges; [e,items) virtual SELF-edges (r=c=item-e,
// weight dinv^2) — used in phase 1 to absorb the diagonal term.
// phase 0: src = g_z0, dst = g_z1, items = e
// phase 1: src = g_z1, dst = outp, items = e + n
// ---------------------------------------------------------------------------
__global__ __launch_bounds__(256) void k_scatter(const int* __restrict__ ebuf,
                                                 float* __restrict__ outp,
                                                 int phase, int e, int items,
                                                 int n) {
    const float4* __restrict__ src =
        (phase == 0) ? reinterpret_cast<const float4*>(g_z0)
                     : reinterpret_cast<const float4*>(g_z1);
    float* __restrict__ dstb = (phase == 0) ? g_z1 : outp;

    long t = (long)blockIdx.x * blockDim.x + threadIdx.x;
    int item = (int)(t >> 1);
    int h    = (int)(t & 1);
    if (item >= items) return;

    int r, c;
    if (item < e) {
        int st = g_stride;
        r = ebuf[(long)item * st];
        c = ebuf[((long)e + item) * st];
        if ((unsigned)r >= (unsigned)n || (unsigned)c >= (unsigned)n) return;
    } else {
        r = c = item - e;          // virtual self-edge: weight = dinv^2
    }
    float w = g_dinv[r] * g_dinv[c];
    float4 v = src[(long)r * 2 + h];
    float* dst = dstb + (long)c * 8 + h * 4;
    asm volatile("red.global.add.v4.f32 [%0], {%1, %2, %3, %4};"
                 :: "l"(dst), "f"(w * v.x), "f"(w * v.y),
                    "f"(w * v.z), "f"(w * v.w)
                 : "memory");
}

// ---------------------------------------------------------------------------
// Launcher (only harness pointers cross the host/device argument boundary)
// ---------------------------------------------------------------------------
extern "C" void kernel_launch(void* const* d_in, const int* in_sizes, int n_in,
                              void* d_out, int out_size) {
    const float* x   = (const float*)d_in[0];
    const int*   ei  = (const int*)d_in[1];   // int32 view; stride handles int64
    const float* W1  = (const float*)d_in[2];
    const float* b1  = (const float*)d_in[3];
    const float* W2  = (const float*)d_in[4];
    const float* b2  = (const float*)d_in[5];
    const float* Wfc = (const float*)d_in[6];
    const float* bfc = (const float*)d_in[7];
    float*       out = (float*)d_out;

    const int n = in_sizes[0] / 128;
    const int e = in_sizes[1] / 2;

    const int T = 256;
    int gn  = (n + T - 1) / T;
    int ge  = (e + T - 1) / T;
    int gz  = (n * 32 + T - 1) / T;                        // warp per row
    int gs0 = (int)(((long)e * 2 + T - 1) / T);            // 2 thr/edge
    int gs1 = (int)(((long)(e + n) * 2 + T - 1) / T);      // + self-edges

    // degrees + fused weight collapse
    k_init<<<gn, T>>>(ei, n);
    k_hist<<<ge, T>>>(ei, e, n);
    k_prep2<<<129, T>>>(W1, W2, Wfc, b1, b2, bfc);

    // z0 = X@Wall ; z1 = c1 + dinv^2 z0 ; out = c2 ; dinv from deg
    k_gz0<<<gz, T>>>(x, out, n);

    // z1 += A-offdiag z0
    k_scatter<<<gs0, T>>>(ei, out, 0, e, e, n);

    // out += A z1  (off-diagonal + virtual self-edges)
    k_scatter<<<gs1, T>>>(ei, out, 1, e, e + n, n);
}